// round 13
// baseline (speedup 1.0000x reference)
#include <cuda_runtime.h>
#include <cuda_bf16.h>
#include <cstdint>
#include <math.h>

#define BB 2
#define CC 512
#define NN 4096          // H*W
#define HID 512
#define NHEADS 8
#define DHEAD 64
#define NGROUPS 32
#define EPS_GN 1e-5f
#define QK_SCALE 0.35355339059327373f   // 64^(-0.25)
#define LOG2E 1.4426950408889634f
#define NBH (BB * NHEADS)               // 16

// ---------------- scratch (allocation-free rule: __device__ globals) ----------
__device__ __nv_bfloat16 g_xnb[BB * NN * CC];     // groupnormed x, transposed [b][n][c]
__device__ __nv_bfloat16 g_aob[BB * NN * HID];    // attention out, transposed [b][n][hid]
__device__ __nv_bfloat16 g_qt[NBH * NN * DHEAD];  // [bh][n][d] (scale QK*log2e)
__device__ __nv_bfloat16 g_kt[NBH * NN * DHEAD];  // [bh][n][d] (scale QK)
__device__ __nv_bfloat16 g_vt[NBH * DHEAD * NN];  // [bh][d][n]
__device__ __nv_bfloat16 g_wqb[HID * CC];
__device__ __nv_bfloat16 g_wkb[HID * CC];
__device__ __nv_bfloat16 g_wvb[HID * CC];
__device__ __nv_bfloat16 g_wob[CC * HID];
__device__ float g_gnpart[BB * NGROUPS * 8 * 2];

// ======================= helpers ==============================================
__device__ __forceinline__ uint32_t smem_u32(const void* p) {
    uint32_t a;
    asm("{ .reg .u64 t; cvta.to.shared.u64 t, %1; cvt.u32.u64 %0, t; }" : "=r"(a) : "l"(p));
    return a;
}
__device__ __forceinline__ uint32_t sw128(uint32_t off) { return off ^ ((off >> 3) & 0x70); }

__device__ __forceinline__ void ldsm_x4(uint32_t* r, uint32_t addr) {
    asm volatile("ldmatrix.sync.aligned.m8n8.x4.shared.b16 {%0,%1,%2,%3}, [%4];"
                 : "=r"(r[0]), "=r"(r[1]), "=r"(r[2]), "=r"(r[3]) : "r"(addr));
}
__device__ __forceinline__ void mma16816(float* c, const uint32_t* a, uint32_t b0, uint32_t b1) {
    asm volatile("mma.sync.aligned.m16n8k16.row.col.f32.bf16.bf16.f32 "
                 "{%0,%1,%2,%3}, {%4,%5,%6,%7}, {%8,%9}, {%0,%1,%2,%3};"
                 : "+f"(c[0]), "+f"(c[1]), "+f"(c[2]), "+f"(c[3])
                 : "r"(a[0]), "r"(a[1]), "r"(a[2]), "r"(a[3]), "r"(b0), "r"(b1));
}
__device__ __forceinline__ uint32_t pack_bf16x2(float lo, float hi) {
    uint32_t d;
    asm("cvt.rn.bf16x2.f32 %0, %1, %2;" : "=r"(d) : "f"(hi), "f"(lo));
    return d;
}
__device__ __forceinline__ unsigned short f2bf(float f) {
    unsigned short u;
    asm("cvt.rn.bf16.f32 %0, %1;" : "=h"(u) : "f"(f));
    return u;
}
__device__ __forceinline__ float ex2(float x) {
    float r;
    asm("ex2.approx.f32 %0, %1;" : "=f"(r) : "f"(x));
    return r;
}
__device__ __forceinline__ void cp16(uint32_t saddr, const void* g) {
    asm volatile("cp.async.cg.shared.global [%0], [%1], 16;" :: "r"(saddr), "l"(g));
}

// ---------------- weight fp32 -> bf16 ----------------------------------------
__global__ void __launch_bounds__(256) wconv_kernel(
    const float* __restrict__ wq, const float* __restrict__ wk,
    const float* __restrict__ wv, const float* __restrict__ wo,
    __nv_bfloat16* __restrict__ oq, __nv_bfloat16* __restrict__ ok,
    __nv_bfloat16* __restrict__ ov, __nv_bfloat16* __restrict__ oo)
{
    int i = blockIdx.x * 256 + threadIdx.x;
    const float4* s[4] = {(const float4*)wq, (const float4*)wk, (const float4*)wv, (const float4*)wo};
    __nv_bfloat16* d[4] = {oq, ok, ov, oo};
    #pragma unroll
    for (int m = 0; m < 4; m++) {
        float4 v = s[m][i];
        uint2 o;
        o.x = pack_bf16x2(v.x, v.y);
        o.y = pack_bf16x2(v.z, v.w);
        *(uint2*)(d[m] + (size_t)i * 4) = o;
    }
}

// ---------------- GroupNorm phase 1: partial stats ----------------------------
__global__ void __launch_bounds__(256) gn_p1_kernel(
    const float* __restrict__ x, float* __restrict__ part)
{
    const int bid = blockIdx.x;
    const int bg = bid >> 3, ch = bid & 7;
    const int b = bg / NGROUPS, g = bg % NGROUPS;
    const int c0 = g * 16;
    const int n0 = ch * 512;
    const float* xp = x + ((size_t)b * CC + c0) * NN;
    const int tid = threadIdx.x;

    float s = 0.f, s2 = 0.f;
    #pragma unroll
    for (int r = 0; r < 16; r++) {
        #pragma unroll 2
        for (int i = tid; i < 512; i += 256) {
            float v = xp[(size_t)r * NN + n0 + i];
            s += v; s2 += v * v;
        }
    }
    __shared__ float sh[512];
    sh[tid] = s; sh[tid + 256] = s2;
    __syncthreads();
    for (int st = 128; st > 0; st >>= 1) {
        if (tid < st) {
            sh[tid]       += sh[tid + st];
            sh[tid + 256] += sh[tid + 256 + st];
        }
        __syncthreads();
    }
    if (tid == 0) {
        part[bid * 2]     = sh[0];
        part[bid * 2 + 1] = sh[256];
    }
}

// ---------------- GroupNorm phase 2: normalize + transpose --------------------
__global__ void __launch_bounds__(256) gn_p2_kernel(
    const float* __restrict__ x, const float* __restrict__ gamma,
    const float* __restrict__ beta, const float* __restrict__ part,
    __nv_bfloat16* __restrict__ xnb)
{
    const int bid = blockIdx.x;
    const int bg = bid >> 3, ch = bid & 7;
    const int b = bg / NGROUPS, g = bg % NGROUPS;
    const int c0 = g * 16;
    const int n0 = ch * 512;
    const float* xp = x + ((size_t)b * CC + c0) * NN;
    const int tid = threadIdx.x;

    float sum = 0.f, ssq = 0.f;
    #pragma unroll
    for (int k = 0; k < 8; k++) {
        sum += part[(bg * 8 + k) * 2];
        ssq += part[(bg * 8 + k) * 2 + 1];
    }
    const float mean = sum * (1.0f / 65536.0f);
    const float var  = ssq * (1.0f / 65536.0f) - mean * mean;
    const float inv  = rsqrtf(var + EPS_GN);

    float ar[16], br[16];
    #pragma unroll
    for (int r = 0; r < 16; r++) {
        float gm = gamma[c0 + r];
        ar[r] = gm * inv;
        br[r] = beta[c0 + r] - mean * gm * inv;
    }

    __shared__ unsigned short T[16][264];
    __nv_bfloat16* dst0 = xnb + (size_t)b * NN * CC + c0;

    #pragma unroll
    for (int half = 0; half < 2; half++) {
        const int nb = n0 + half * 256;
        #pragma unroll
        for (int r = 0; r < 16; r++)
            T[r][tid] = f2bf(xp[(size_t)r * NN + nb + tid] * ar[r] + br[r]);
        __syncthreads();
        uint32_t u[8];
        #pragma unroll
        for (int j = 0; j < 8; j++)
            u[j] = (uint32_t)T[2 * j][tid] | ((uint32_t)T[2 * j + 1][tid] << 16);
        uint4* dp = (uint4*)(dst0 + (size_t)(nb + tid) * CC);
        dp[0] = make_uint4(u[0], u[1], u[2], u[3]);
        dp[1] = make_uint4(u[4], u[5], u[6], u[7]);
        __syncthreads();
    }
}

// ---------------- HMMA GEMM (3-stage, fully unrolled, reg-capped) --------------
// MODE 0: grid.y=12 -> q (scale QK*log2e), k (scale QK), v ([d][n])
// MODE 2: grid.y=4  -> o-proj: fp32 out + bias + residual
#define HG_DSMEM (3 * 32768 + 1024)

template<int MODE>
__global__ void __launch_bounds__(256, 2) hgemm_kernel(
    const __nv_bfloat16* __restrict__ Wq, const float* __restrict__ Bq,
    const __nv_bfloat16* __restrict__ Wk, const float* __restrict__ Bk,
    const __nv_bfloat16* __restrict__ Wv, const float* __restrict__ Bv,
    const __nv_bfloat16* __restrict__ X,
    __nv_bfloat16* __restrict__ Oq, __nv_bfloat16* __restrict__ Ok,
    __nv_bfloat16* __restrict__ Ov,
    const float* __restrict__ resid, float* __restrict__ Of)
{
    extern __shared__ char dsm[];
    const int tid = threadIdx.x, lane = tid & 31, w = tid >> 5;
    const int wm = w >> 2, wn = w & 3;
    const int n0 = blockIdx.x * 128;
    const int ty = blockIdx.y;
    const int b = blockIdx.z;

    int sel, mt;
    const __nv_bfloat16* W;
    const float* bias;
    if (MODE == 0) {
        sel = ty >> 2; mt = ty & 3;
        W = (sel == 0) ? Wq : (sel == 1) ? Wk : Wv;
        bias = (sel == 0) ? Bq : (sel == 1) ? Bk : Bv;
    } else {
        sel = 0; mt = ty; W = Wq; bias = Bq;
    }
    const int m0 = mt * 128;
    const __nv_bfloat16* Xb = X + (size_t)b * NN * CC;

    const uint32_t sb_raw = smem_u32(dsm);
    const uint32_t sb = (sb_raw + 1023u) & ~1023u;
    char* smem = dsm + (sb - sb_raw);

    auto issue = [&](int kt, int s) {
        const int k0 = kt * 64;
        uint32_t abase = sb + (uint32_t)s * 32768;
        uint32_t bbase = abase + 16384;
        #pragma unroll
        for (int i = 0; i < 4; i++) {
            int c = tid + i * 256;
            int row = c >> 3, col = c & 7;
            cp16(abase + sw128((uint32_t)(row * 128 + col * 16)),
                 W + (size_t)(m0 + row) * CC + k0 + col * 8);
            cp16(bbase + sw128((uint32_t)(row * 128 + col * 16)),
                 Xb + (size_t)(n0 + row) * CC + k0 + col * 8);
        }
        asm volatile("cp.async.commit_group;" ::: "memory");
    };

    issue(0, 0);
    issue(1, 1);

    float acc[4][4][4] = {};

    #pragma unroll
    for (int kt = 0; kt < 8; kt++) {           // fully unrolled -> static stages
        if (kt < 7) asm volatile("cp.async.wait_group 1;" ::: "memory");
        else        asm volatile("cp.async.wait_group 0;" ::: "memory");
        __syncthreads();
        if (kt + 2 < 8) issue(kt + 2, (kt + 2) % 3);
        const uint32_t abase = sb + (uint32_t)(kt % 3) * 32768;
        const uint32_t bbase = abase + 16384;
        #pragma unroll
        for (int ks = 0; ks < 4; ks++) {
            uint32_t af[4][4];
            #pragma unroll
            for (int mf = 0; mf < 4; mf++) {
                uint32_t addr = abase + sw128((uint32_t)(
                    (wm * 64 + mf * 16 + (lane & 15)) * 128 + ((lane >> 4) & 1) * 16 + ks * 32));
                ldsm_x4(af[mf], addr);
            }
            #pragma unroll
            for (int nf = 0; nf < 2; nf++) {
                uint32_t r[4];
                uint32_t addr = bbase + sw128((uint32_t)(
                    (wn * 32 + nf * 16 + ((lane >> 4) << 3) + (lane & 7)) * 128 +
                    ((lane >> 3) & 1) * 16 + ks * 32));
                ldsm_x4(r, addr);
                #pragma unroll
                for (int mf = 0; mf < 4; mf++) {
                    mma16816(acc[mf][nf * 2],     af[mf], r[0], r[1]);
                    mma16816(acc[mf][nf * 2 + 1], af[mf], r[2], r[3]);
                }
            }
        }
    }
    __syncthreads();   // all compute done before smem reuse in epilogue

    float bias_r[4][2];
    #pragma unroll
    for (int mf = 0; mf < 4; mf++) {
        int m = m0 + wm * 64 + mf * 16 + (lane >> 2);
        bias_r[mf][0] = bias[m];
        bias_r[mf][1] = bias[m + 8];
    }

    if (MODE == 2) {
        float* outp = Of + (size_t)b * CC * NN;
        const float* resb = resid + (size_t)b * CC * NN;
        #pragma unroll
        for (int mf = 0; mf < 4; mf++)
        #pragma unroll
        for (int n8 = 0; n8 < 4; n8++) {
            int rrow = m0 + wm * 64 + mf * 16 + (lane >> 2);
            int col = n0 + wn * 32 + n8 * 8 + (lane & 3) * 2;
            size_t i0x = (size_t)rrow * NN + col;
            size_t i1x = (size_t)(rrow + 8) * NN + col;
            float2 r0 = *(const float2*)(resb + i0x);
            float2 r1 = *(const float2*)(resb + i1x);
            float2 o0 = make_float2(acc[mf][n8][0] + bias_r[mf][0] + r0.x,
                                    acc[mf][n8][1] + bias_r[mf][0] + r0.y);
            float2 o1 = make_float2(acc[mf][n8][2] + bias_r[mf][1] + r1.x,
                                    acc[mf][n8][3] + bias_r[mf][1] + r1.y);
            *(float2*)(outp + i0x) = o0;
            *(float2*)(outp + i1x) = o1;
        }
    } else {
        const float scale = (sel == 0) ? QK_SCALE * LOG2E : QK_SCALE;
        unsigned short* Osm = (unsigned short*)smem;   // [128][136]
        if (sel < 2) {
            // stage transposed: Osm[n][m]
            #pragma unroll
            for (int mf = 0; mf < 4; mf++)
            #pragma unroll
            for (int n8 = 0; n8 < 4; n8++) {
                int rrow = wm * 64 + mf * 16 + (lane >> 2);
                int col = wn * 32 + n8 * 8 + (lane & 3) * 2;
                Osm[col * 136 + rrow]           = f2bf((acc[mf][n8][0] + bias_r[mf][0]) * scale);
                Osm[(col + 1) * 136 + rrow]     = f2bf((acc[mf][n8][1] + bias_r[mf][0]) * scale);
                Osm[col * 136 + rrow + 8]       = f2bf((acc[mf][n8][2] + bias_r[mf][1]) * scale);
                Osm[(col + 1) * 136 + rrow + 8] = f2bf((acc[mf][n8][3] + bias_r[mf][1]) * scale);
            }
            __syncthreads();
            int n = tid >> 1, half = tid & 1;
            int head = mt * 2 + half;
            __nv_bfloat16* outp = ((sel == 0) ? Oq : Ok) +
                ((size_t)(b * NHEADS + head) * NN + (n0 + n)) * 64;
            const uint4* src = (const uint4*)(Osm + n * 136 + half * 64);
            #pragma unroll
            for (int i = 0; i < 8; i++) ((uint4*)outp)[i] = src[i];
        } else {
            // v: stage natural: Osm[m][n]
            #pragma unroll
            for (int mf = 0; mf < 4; mf++)
            #pragma unroll
            for (int n8 = 0; n8 < 4; n8++) {
                int rrow = wm * 64 + mf * 16 + (lane >> 2);
                int col = wn * 32 + n8 * 8 + (lane & 3) * 2;
                *(uint32_t*)(Osm + rrow * 136 + col) =
                    pack_bf16x2(acc[mf][n8][0] + bias_r[mf][0], acc[mf][n8][1] + bias_r[mf][0]);
                *(uint32_t*)(Osm + (rrow + 8) * 136 + col) =
                    pack_bf16x2(acc[mf][n8][2] + bias_r[mf][1], acc[mf][n8][3] + bias_r[mf][1]);
            }
            __syncthreads();
            int m = tid >> 1, half = tid & 1;
            int mm = m0 + m;
            __nv_bfloat16* outp = Ov +
                ((size_t)(b * NHEADS + (mm >> 6)) * 64 + (mm & 63)) * NN + n0 + half * 64;
            const uint4* src = (const uint4*)(Osm + m * 136 + half * 64);
            #pragma unroll
            for (int i = 0; i < 8; i++) ((uint4*)outp)[i] = src[i];
        }
    }
}

// ---------------- HMMA flash attention (32 rows/warp, shared K/V frags) --------
// BM=128 q-rows/CTA (4 warps x 32 rows), BN=64, 3-stage cp.async, 3 CTAs/SM.
// Each K/V ldsm feeds 4 MMAs (2 M-frags) -> smem read traffic per output halved.
#define A_STAGES 3
#define A_STAGE_BYTES 16384
#define A_SMEM (A_STAGES * A_STAGE_BYTES + 1024)

__global__ void __launch_bounds__(128, 3) attn_mma_kernel(
    const __nv_bfloat16* __restrict__ qt,
    const __nv_bfloat16* __restrict__ kt,
    const __nv_bfloat16* __restrict__ vt,
    __nv_bfloat16* __restrict__ aob)
{
    extern __shared__ char dsm[];
    const uint32_t sb_raw = smem_u32(dsm);
    const uint32_t sb = (sb_raw + 1023u) & ~1023u;
    char* smem = dsm + (sb - sb_raw);

    const int tid = threadIdx.x;
    const int lane = tid & 31;
    const int w = tid >> 5;                    // 0..3: rows [w*32, w*32+32)
    const int i0 = blockIdx.x * 128;
    const int bh = blockIdx.y;

    const __nv_bfloat16* Qg = qt + (size_t)bh * NN * 64;
    const __nv_bfloat16* Kg = kt + (size_t)bh * NN * 64;
    const __nv_bfloat16* Vg = vt + (size_t)bh * 64 * NN;

    // ---- stage Q (128 rows x 128B = stage-0 16KB), load A-frags ----
    #pragma unroll
    for (int i = 0; i < 8; i++) {
        int c = tid + i * 128;                 // 1024 chunks
        int row = c >> 3, col = c & 7;
        cp16(sb + sw128((uint32_t)(row * 128 + col * 16)),
             Qg + (size_t)(i0 + row) * 64 + col * 8);
    }
    asm volatile("cp.async.commit_group;" ::: "memory");
    asm volatile("cp.async.wait_group 0;" ::: "memory");
    __syncthreads();
    uint32_t qf[4][2][4];
    #pragma unroll
    for (int ks = 0; ks < 4; ks++)
        #pragma unroll
        for (int mf = 0; mf < 2; mf++) {
            uint32_t addr = sb + sw128((uint32_t)(
                (w * 32 + mf * 16 + (lane & 15)) * 128 + ((lane >> 4) & 1) * 16 + ks * 32));
            ldsm_x4(qf[ks][mf], addr);
        }
    __syncthreads();    // Q reads complete before stage-0 K/V overwrites

    auto issue = [&](int it, int s) {
        uint32_t kb = sb + (uint32_t)s * A_STAGE_BYTES;
        uint32_t vb = kb + 8192;
        const int j0 = it * 64;
        #pragma unroll
        for (int i = 0; i < 4; i++) {
            int c = tid + i * 128;
            int row = c >> 3, col = c & 7;
            uint32_t off = sw128((uint32_t)(row * 128 + col * 16));
            cp16(kb + off, Kg + (size_t)(j0 + row) * 64 + col * 8);
            cp16(vb + off, Vg + (size_t)row * NN + j0 + col * 8);
        }
        asm volatile("cp.async.commit_group;" ::: "memory");
    };

    issue(0, 0);
    issue(1, 1);

    float oacc[2][8][4] = {};
    float lsum[2][2] = {};

    const int NITER = NN / 64;   // 64
    int stage = 0;
    for (int it = 0; it < NITER; it++) {
        if (it < NITER - 1) asm volatile("cp.async.wait_group 1;" ::: "memory");
        else                asm volatile("cp.async.wait_group 0;" ::: "memory");
        __syncthreads();
        if (it + 2 < NITER) {
            int s2 = stage + 2; if (s2 >= A_STAGES) s2 -= A_STAGES;
            issue(it + 2, s2);
        }
        const uint32_t kb = sb + (uint32_t)stage * A_STAGE_BYTES;
        const uint32_t vb = kb + 8192;

        // ---- MMA1: S[32 rows][64 j]; each K ldsm feeds both M-frags ----
        float sacc[2][8][4] = {};
        #pragma unroll
        for (int ks = 0; ks < 4; ks++) {
            #pragma unroll
            for (int p = 0; p < 4; p++) {
                uint32_t r[4];
                uint32_t addr = kb + sw128((uint32_t)(
                    (p * 16 + ((lane >> 4) << 3) + (lane & 7)) * 128 +
                    ((lane >> 3) & 1) * 16 + ks * 32));
                ldsm_x4(r, addr);
                #pragma unroll
                for (int mf = 0; mf < 2; mf++) {
                    mma16816(sacc[mf][2 * p],     qf[ks][mf], r[0], r[1]);
                    mma16816(sacc[mf][2 * p + 1], qf[ks][mf], r[2], r[3]);
                }
            }
        }

        // ---- per-jk: exp (ex2), pack, MMA2; each V ldsm feeds both M-frags ----
        #pragma unroll
        for (int jk = 0; jk < 4; jk++) {
            uint32_t pa[2][4];
            #pragma unroll
            for (int mf = 0; mf < 2; mf++) {
                float e0 = ex2(sacc[mf][2 * jk][0]);
                float e1 = ex2(sacc[mf][2 * jk][1]);
                float e2 = ex2(sacc[mf][2 * jk][2]);
                float e3 = ex2(sacc[mf][2 * jk][3]);
                float e4 = ex2(sacc[mf][2 * jk + 1][0]);
                float e5 = ex2(sacc[mf][2 * jk + 1][1]);
                float e6 = ex2(sacc[mf][2 * jk + 1][2]);
                float e7 = ex2(sacc[mf][2 * jk + 1][3]);
                lsum[mf][0] += (e0 + e1) + (e4 + e5);
                lsum[mf][1] += (e2 + e3) + (e6 + e7);
                pa[mf][0] = pack_bf16x2(e0, e1);
                pa[mf][1] = pack_bf16x2(e2, e3);
                pa[mf][2] = pack_bf16x2(e4, e5);
                pa[mf][3] = pack_bf16x2(e6, e7);
            }
            #pragma unroll
            for (int p = 0; p < 4; p++) {
                uint32_t r[4];
                uint32_t addr = vb + sw128((uint32_t)(
                    (p * 16 + ((lane >> 4) << 3) + (lane & 7)) * 128 +
                    ((lane >> 3) & 1) * 16 + jk * 32));
                ldsm_x4(r, addr);
                #pragma unroll
                for (int mf = 0; mf < 2; mf++) {
                    mma16816(oacc[mf][2 * p],     pa[mf], r[0], r[1]);
                    mma16816(oacc[mf][2 * p + 1], pa[mf], r[2], r[3]);
                }
            }
        }
        if (++stage >= A_STAGES) stage = 0;
    }

    // ---- epilogue: quad-reduce lsum, normalize, write transposed bf16 ----
    #pragma unroll
    for (int mf = 0; mf < 2; mf++)
        #pragma unroll
        for (int h = 0; h < 2; h++) {
            lsum[mf][h] += __shfl_xor_sync(0xffffffffu, lsum[mf][h], 1);
            lsum[mf][h] += __shfl_xor_sync(0xffffffffu, lsum[mf][h], 2);
        }

    const int bq = bh >> 3, head = bh & 7;
    __nv_bfloat16* outp = aob + (size_t)bq * NN * HID + head * 64;
    #pragma unroll
    for (int mf = 0; mf < 2; mf++) {
        const float inv0 = 1.0f / lsum[mf][0];
        const float inv1 = 1.0f / lsum[mf][1];
        const int irow = i0 + w * 32 + mf * 16 + (lane >> 2);
        #pragma unroll
        for (int t = 0; t < 8; t++) {
            int d = t * 8 + (lane & 3) * 2;
            *(uint32_t*)(outp + (size_t)irow * HID + d) =
                pack_bf16x2(oacc[mf][t][0] * inv0, oacc[mf][t][1] * inv0);
            *(uint32_t*)(outp + (size_t)(irow + 8) * HID + d) =
                pack_bf16x2(oacc[mf][t][2] * inv1, oacc[mf][t][3] * inv1);
        }
    }
}

// ---------------- launch -----------------------------------------------------
extern "C" void kernel_launch(void* const* d_in, const int* in_sizes, int n_in,
                              void* d_out, int out_size)
{
    const float* x     = (const float*)d_in[0];
    const float* gamma = (const float*)d_in[1];
    const float* beta  = (const float*)d_in[2];
    const float* wq    = (const float*)d_in[3];
    const float* bq    = (const float*)d_in[4];
    const float* wk    = (const float*)d_in[5];
    const float* bk    = (const float*)d_in[6];
    const float* wv    = (const float*)d_in[7];
    const float* bv    = (const float*)d_in[8];
    const float* wo    = (const float*)d_in[9];
    const float* bo    = (const float*)d_in[10];
    float* out = (float*)d_out;

    __nv_bfloat16 *xnb, *aob, *qt, *kt, *vt, *wqb, *wkb, *wvb, *wob;
    float* gnpart;
    cudaGetSymbolAddress((void**)&xnb, g_xnb);
    cudaGetSymbolAddress((void**)&aob, g_aob);
    cudaGetSymbolAddress((void**)&qt,  g_qt);
    cudaGetSymbolAddress((void**)&kt,  g_kt);
    cudaGetSymbolAddress((void**)&vt,  g_vt);
    cudaGetSymbolAddress((void**)&wqb, g_wqb);
    cudaGetSymbolAddress((void**)&wkb, g_wkb);
    cudaGetSymbolAddress((void**)&wvb, g_wvb);
    cudaGetSymbolAddress((void**)&wob, g_wob);
    cudaGetSymbolAddress((void**)&gnpart, g_gnpart);

    cudaFuncSetAttribute(hgemm_kernel<0>,
                         cudaFuncAttributeMaxDynamicSharedMemorySize, HG_DSMEM);
    cudaFuncSetAttribute(hgemm_kernel<2>,
                         cudaFuncAttributeMaxDynamicSharedMemorySize, HG_DSMEM);
    cudaFuncSetAttribute(attn_mma_kernel,
                         cudaFuncAttributeMaxDynamicSharedMemorySize, A_SMEM);

    wconv_kernel<<<256, 256>>>(wq, wk, wv, wo, wqb, wkb, wvb, wob);
    gn_p1_kernel<<<BB * NGROUPS * 8, 256>>>(x, gnpart);
    gn_p2_kernel<<<BB * NGROUPS * 8, 256>>>(x, gamma, beta, gnpart, xnb);

    hgemm_kernel<0><<<dim3(NN / 128, 12, BB), 256, HG_DSMEM>>>(
        wqb, bq, wkb, bk, wvb, bv, xnb, qt, kt, vt, nullptr, nullptr);

    attn_mma_kernel<<<dim3(NN / 128, NBH), 128, A_SMEM>>>(qt, kt, vt, aob);

    hgemm_kernel<2><<<dim3(NN / 128, 4, BB), 256, HG_DSMEM>>>(
        wob, bo, nullptr, nullptr, nullptr, nullptr, aob, nullptr, nullptr, nullptr, x, out);
}

// round 14
// speedup vs baseline: 1.0278x; 1.0278x over previous
#include <cuda_runtime.h>
#include <cuda_bf16.h>
#include <cstdint>
#include <math.h>

#define BB 2
#define CC 512
#define NN 4096          // H*W
#define HID 512
#define NHEADS 8
#define DHEAD 64
#define NGROUPS 32
#define EPS_GN 1e-5f
#define QK_SCALE 0.35355339059327373f   // 64^(-0.25)
#define LOG2E 1.4426950408889634f
#define NBH (BB * NHEADS)               // 16

// ---------------- scratch (allocation-free rule: __device__ globals) ----------
__device__ __nv_bfloat16 g_xnb[BB * NN * CC];     // groupnormed x, transposed [b][n][c]
__device__ __nv_bfloat16 g_aob[BB * NN * HID];    // attention out, transposed [b][n][hid]
__device__ __nv_bfloat16 g_qt[NBH * NN * DHEAD];  // [bh][n][d] (scale QK*log2e)
__device__ __nv_bfloat16 g_kt[NBH * NN * DHEAD];  // [bh][n][d] (scale QK)
__device__ __nv_bfloat16 g_vt[NBH * DHEAD * NN];  // [bh][d][n]
__device__ __nv_bfloat16 g_wqb[HID * CC];
__device__ __nv_bfloat16 g_wkb[HID * CC];
__device__ __nv_bfloat16 g_wvb[HID * CC];
__device__ __nv_bfloat16 g_wob[CC * HID];
__device__ float g_gnpart[BB * NGROUPS * 8 * 2];

// ======================= helpers ==============================================
__device__ __forceinline__ uint32_t smem_u32(const void* p) {
    uint32_t a;
    asm("{ .reg .u64 t; cvta.to.shared.u64 t, %1; cvt.u32.u64 %0, t; }" : "=r"(a) : "l"(p));
    return a;
}
__device__ __forceinline__ uint32_t sw128(uint32_t off) { return off ^ ((off >> 3) & 0x70); }

__device__ __forceinline__ void ldsm_x4(uint32_t* r, uint32_t addr) {
    asm volatile("ldmatrix.sync.aligned.m8n8.x4.shared.b16 {%0,%1,%2,%3}, [%4];"
                 : "=r"(r[0]), "=r"(r[1]), "=r"(r[2]), "=r"(r[3]) : "r"(addr));
}
__device__ __forceinline__ void mma16816(float* c, const uint32_t* a, uint32_t b0, uint32_t b1) {
    asm volatile("mma.sync.aligned.m16n8k16.row.col.f32.bf16.bf16.f32 "
                 "{%0,%1,%2,%3}, {%4,%5,%6,%7}, {%8,%9}, {%0,%1,%2,%3};"
                 : "+f"(c[0]), "+f"(c[1]), "+f"(c[2]), "+f"(c[3])
                 : "r"(a[0]), "r"(a[1]), "r"(a[2]), "r"(a[3]), "r"(b0), "r"(b1));
}
__device__ __forceinline__ uint32_t pack_bf16x2(float lo, float hi) {
    uint32_t d;
    asm("cvt.rn.bf16x2.f32 %0, %1, %2;" : "=r"(d) : "f"(hi), "f"(lo));
    return d;
}
__device__ __forceinline__ unsigned short f2bf(float f) {
    unsigned short u;
    asm("cvt.rn.bf16.f32 %0, %1;" : "=h"(u) : "f"(f));
    return u;
}
__device__ __forceinline__ float ex2(float x) {
    float r;
    asm("ex2.approx.f32 %0, %1;" : "=f"(r) : "f"(x));
    return r;
}
__device__ __forceinline__ void cp16(uint32_t saddr, const void* g) {
    asm volatile("cp.async.cg.shared.global [%0], [%1], 16;" :: "r"(saddr), "l"(g));
}

// ---------------- weight fp32 -> bf16 ----------------------------------------
__global__ void __launch_bounds__(256) wconv_kernel(
    const float* __restrict__ wq, const float* __restrict__ wk,
    const float* __restrict__ wv, const float* __restrict__ wo,
    __nv_bfloat16* __restrict__ oq, __nv_bfloat16* __restrict__ ok,
    __nv_bfloat16* __restrict__ ov, __nv_bfloat16* __restrict__ oo)
{
    int i = blockIdx.x * 256 + threadIdx.x;
    const float4* s[4] = {(const float4*)wq, (const float4*)wk, (const float4*)wv, (const float4*)wo};
    __nv_bfloat16* d[4] = {oq, ok, ov, oo};
    #pragma unroll
    for (int m = 0; m < 4; m++) {
        float4 v = s[m][i];
        uint2 o;
        o.x = pack_bf16x2(v.x, v.y);
        o.y = pack_bf16x2(v.z, v.w);
        *(uint2*)(d[m] + (size_t)i * 4) = o;
    }
}

// ---------------- GroupNorm phase 1: partial stats ----------------------------
__global__ void __launch_bounds__(256) gn_p1_kernel(
    const float* __restrict__ x, float* __restrict__ part)
{
    const int bid = blockIdx.x;
    const int bg = bid >> 3, ch = bid & 7;
    const int b = bg / NGROUPS, g = bg % NGROUPS;
    const int c0 = g * 16;
    const int n0 = ch * 512;
    const float* xp = x + ((size_t)b * CC + c0) * NN;
    const int tid = threadIdx.x;

    float s = 0.f, s2 = 0.f;
    #pragma unroll
    for (int r = 0; r < 16; r++) {
        #pragma unroll 2
        for (int i = tid; i < 512; i += 256) {
            float v = xp[(size_t)r * NN + n0 + i];
            s += v; s2 += v * v;
        }
    }
    __shared__ float sh[512];
    sh[tid] = s; sh[tid + 256] = s2;
    __syncthreads();
    for (int st = 128; st > 0; st >>= 1) {
        if (tid < st) {
            sh[tid]       += sh[tid + st];
            sh[tid + 256] += sh[tid + 256 + st];
        }
        __syncthreads();
    }
    if (tid == 0) {
        part[bid * 2]     = sh[0];
        part[bid * 2 + 1] = sh[256];
    }
}

// ---------------- GroupNorm phase 2: normalize + transpose --------------------
__global__ void __launch_bounds__(256) gn_p2_kernel(
    const float* __restrict__ x, const float* __restrict__ gamma,
    const float* __restrict__ beta, const float* __restrict__ part,
    __nv_bfloat16* __restrict__ xnb)
{
    const int bid = blockIdx.x;
    const int bg = bid >> 3, ch = bid & 7;
    const int b = bg / NGROUPS, g = bg % NGROUPS;
    const int c0 = g * 16;
    const int n0 = ch * 512;
    const float* xp = x + ((size_t)b * CC + c0) * NN;
    const int tid = threadIdx.x;

    float sum = 0.f, ssq = 0.f;
    #pragma unroll
    for (int k = 0; k < 8; k++) {
        sum += part[(bg * 8 + k) * 2];
        ssq += part[(bg * 8 + k) * 2 + 1];
    }
    const float mean = sum * (1.0f / 65536.0f);
    const float var  = ssq * (1.0f / 65536.0f) - mean * mean;
    const float inv  = rsqrtf(var + EPS_GN);

    float ar[16], br[16];
    #pragma unroll
    for (int r = 0; r < 16; r++) {
        float gm = gamma[c0 + r];
        ar[r] = gm * inv;
        br[r] = beta[c0 + r] - mean * gm * inv;
    }

    __shared__ unsigned short T[16][264];
    __nv_bfloat16* dst0 = xnb + (size_t)b * NN * CC + c0;

    #pragma unroll
    for (int half = 0; half < 2; half++) {
        const int nb = n0 + half * 256;
        #pragma unroll
        for (int r = 0; r < 16; r++)
            T[r][tid] = f2bf(xp[(size_t)r * NN + nb + tid] * ar[r] + br[r]);
        __syncthreads();
        uint32_t u[8];
        #pragma unroll
        for (int j = 0; j < 8; j++)
            u[j] = (uint32_t)T[2 * j][tid] | ((uint32_t)T[2 * j + 1][tid] << 16);
        uint4* dp = (uint4*)(dst0 + (size_t)(nb + tid) * CC);
        dp[0] = make_uint4(u[0], u[1], u[2], u[3]);
        dp[1] = make_uint4(u[4], u[5], u[6], u[7]);
        __syncthreads();
    }
}

// ---------------- HMMA GEMM (3-stage, fully unrolled, reg-capped) --------------
// MODE 0: grid.y=12 -> q (scale QK*log2e), k (scale QK), v ([d][n])
// MODE 2: grid.y=4  -> o-proj: fp32 out + bias + residual
#define HG_DSMEM (3 * 32768 + 1024)

template<int MODE>
__global__ void __launch_bounds__(256, 2) hgemm_kernel(
    const __nv_bfloat16* __restrict__ Wq, const float* __restrict__ Bq,
    const __nv_bfloat16* __restrict__ Wk, const float* __restrict__ Bk,
    const __nv_bfloat16* __restrict__ Wv, const float* __restrict__ Bv,
    const __nv_bfloat16* __restrict__ X,
    __nv_bfloat16* __restrict__ Oq, __nv_bfloat16* __restrict__ Ok,
    __nv_bfloat16* __restrict__ Ov,
    const float* __restrict__ resid, float* __restrict__ Of)
{
    extern __shared__ char dsm[];
    const int tid = threadIdx.x, lane = tid & 31, w = tid >> 5;
    const int wm = w >> 2, wn = w & 3;
    const int n0 = blockIdx.x * 128;
    const int ty = blockIdx.y;
    const int b = blockIdx.z;

    int sel, mt;
    const __nv_bfloat16* W;
    const float* bias;
    if (MODE == 0) {
        sel = ty >> 2; mt = ty & 3;
        W = (sel == 0) ? Wq : (sel == 1) ? Wk : Wv;
        bias = (sel == 0) ? Bq : (sel == 1) ? Bk : Bv;
    } else {
        sel = 0; mt = ty; W = Wq; bias = Bq;
    }
    const int m0 = mt * 128;
    const __nv_bfloat16* Xb = X + (size_t)b * NN * CC;

    const uint32_t sb_raw = smem_u32(dsm);
    const uint32_t sb = (sb_raw + 1023u) & ~1023u;
    char* smem = dsm + (sb - sb_raw);

    auto issue = [&](int kt, int s) {
        const int k0 = kt * 64;
        uint32_t abase = sb + (uint32_t)s * 32768;
        uint32_t bbase = abase + 16384;
        #pragma unroll
        for (int i = 0; i < 4; i++) {
            int c = tid + i * 256;
            int row = c >> 3, col = c & 7;
            cp16(abase + sw128((uint32_t)(row * 128 + col * 16)),
                 W + (size_t)(m0 + row) * CC + k0 + col * 8);
            cp16(bbase + sw128((uint32_t)(row * 128 + col * 16)),
                 Xb + (size_t)(n0 + row) * CC + k0 + col * 8);
        }
        asm volatile("cp.async.commit_group;" ::: "memory");
    };

    issue(0, 0);
    issue(1, 1);

    float acc[4][4][4] = {};

    #pragma unroll
    for (int kt = 0; kt < 8; kt++) {           // fully unrolled -> static stages
        if (kt < 7) asm volatile("cp.async.wait_group 1;" ::: "memory");
        else        asm volatile("cp.async.wait_group 0;" ::: "memory");
        __syncthreads();
        if (kt + 2 < 8) issue(kt + 2, (kt + 2) % 3);
        const uint32_t abase = sb + (uint32_t)(kt % 3) * 32768;
        const uint32_t bbase = abase + 16384;
        #pragma unroll
        for (int ks = 0; ks < 4; ks++) {
            uint32_t af[4][4];
            #pragma unroll
            for (int mf = 0; mf < 4; mf++) {
                uint32_t addr = abase + sw128((uint32_t)(
                    (wm * 64 + mf * 16 + (lane & 15)) * 128 + ((lane >> 4) & 1) * 16 + ks * 32));
                ldsm_x4(af[mf], addr);
            }
            #pragma unroll
            for (int nf = 0; nf < 2; nf++) {
                uint32_t r[4];
                uint32_t addr = bbase + sw128((uint32_t)(
                    (wn * 32 + nf * 16 + ((lane >> 4) << 3) + (lane & 7)) * 128 +
                    ((lane >> 3) & 1) * 16 + ks * 32));
                ldsm_x4(r, addr);
                #pragma unroll
                for (int mf = 0; mf < 4; mf++) {
                    mma16816(acc[mf][nf * 2],     af[mf], r[0], r[1]);
                    mma16816(acc[mf][nf * 2 + 1], af[mf], r[2], r[3]);
                }
            }
        }
    }
    __syncthreads();   // all compute done before smem reuse in epilogue

    float bias_r[4][2];
    #pragma unroll
    for (int mf = 0; mf < 4; mf++) {
        int m = m0 + wm * 64 + mf * 16 + (lane >> 2);
        bias_r[mf][0] = bias[m];
        bias_r[mf][1] = bias[m + 8];
    }

    if (MODE == 2) {
        float* outp = Of + (size_t)b * CC * NN;
        const float* resb = resid + (size_t)b * CC * NN;
        #pragma unroll
        for (int mf = 0; mf < 4; mf++)
        #pragma unroll
        for (int n8 = 0; n8 < 4; n8++) {
            int rrow = m0 + wm * 64 + mf * 16 + (lane >> 2);
            int col = n0 + wn * 32 + n8 * 8 + (lane & 3) * 2;
            size_t i0x = (size_t)rrow * NN + col;
            size_t i1x = (size_t)(rrow + 8) * NN + col;
            float2 r0 = *(const float2*)(resb + i0x);
            float2 r1 = *(const float2*)(resb + i1x);
            float2 o0 = make_float2(acc[mf][n8][0] + bias_r[mf][0] + r0.x,
                                    acc[mf][n8][1] + bias_r[mf][0] + r0.y);
            float2 o1 = make_float2(acc[mf][n8][2] + bias_r[mf][1] + r1.x,
                                    acc[mf][n8][3] + bias_r[mf][1] + r1.y);
            *(float2*)(outp + i0x) = o0;
            *(float2*)(outp + i1x) = o1;
        }
    } else {
        const float scale = (sel == 0) ? QK_SCALE * LOG2E : QK_SCALE;
        unsigned short* Osm = (unsigned short*)smem;   // [128][136]
        if (sel < 2) {
            // stage transposed: Osm[n][m]
            #pragma unroll
            for (int mf = 0; mf < 4; mf++)
            #pragma unroll
            for (int n8 = 0; n8 < 4; n8++) {
                int rrow = wm * 64 + mf * 16 + (lane >> 2);
                int col = wn * 32 + n8 * 8 + (lane & 3) * 2;
                Osm[col * 136 + rrow]           = f2bf((acc[mf][n8][0] + bias_r[mf][0]) * scale);
                Osm[(col + 1) * 136 + rrow]     = f2bf((acc[mf][n8][1] + bias_r[mf][0]) * scale);
                Osm[col * 136 + rrow + 8]       = f2bf((acc[mf][n8][2] + bias_r[mf][1]) * scale);
                Osm[(col + 1) * 136 + rrow + 8] = f2bf((acc[mf][n8][3] + bias_r[mf][1]) * scale);
            }
            __syncthreads();
            int n = tid >> 1, half = tid & 1;
            int head = mt * 2 + half;
            __nv_bfloat16* outp = ((sel == 0) ? Oq : Ok) +
                ((size_t)(b * NHEADS + head) * NN + (n0 + n)) * 64;
            const uint4* src = (const uint4*)(Osm + n * 136 + half * 64);
            #pragma unroll
            for (int i = 0; i < 8; i++) ((uint4*)outp)[i] = src[i];
        } else {
            // v: stage natural: Osm[m][n]
            #pragma unroll
            for (int mf = 0; mf < 4; mf++)
            #pragma unroll
            for (int n8 = 0; n8 < 4; n8++) {
                int rrow = wm * 64 + mf * 16 + (lane >> 2);
                int col = wn * 32 + n8 * 8 + (lane & 3) * 2;
                *(uint32_t*)(Osm + rrow * 136 + col) =
                    pack_bf16x2(acc[mf][n8][0] + bias_r[mf][0], acc[mf][n8][1] + bias_r[mf][0]);
                *(uint32_t*)(Osm + (rrow + 8) * 136 + col) =
                    pack_bf16x2(acc[mf][n8][2] + bias_r[mf][1], acc[mf][n8][3] + bias_r[mf][1]);
            }
            __syncthreads();
            int m = tid >> 1, half = tid & 1;
            int mm = m0 + m;
            __nv_bfloat16* outp = Ov +
                ((size_t)(b * NHEADS + (mm >> 6)) * 64 + (mm & 63)) * NN + n0 + half * 64;
            const uint4* src = (const uint4*)(Osm + m * 136 + half * 64);
            #pragma unroll
            for (int i = 0; i < 8; i++) ((uint4*)outp)[i] = src[i];
        }
    }
}

// ---------------- HMMA flash attention (32 rows/warp, jk-halved sacc) ----------
// BM=128 q-rows/CTA (4 warps x 32 rows), BN=64, 3-stage cp.async, 3 CTAs/SM.
// Each K/V ldsm feeds 2 M-frags; j processed in two halves so sacc is only
// [2][4][4] = 32 regs live -> peak ~150 regs, no spills at the 170 cap.
#define A_STAGES 3
#define A_STAGE_BYTES 16384
#define A_SMEM (A_STAGES * A_STAGE_BYTES + 1024)

__global__ void __launch_bounds__(128, 3) attn_mma_kernel(
    const __nv_bfloat16* __restrict__ qt,
    const __nv_bfloat16* __restrict__ kt,
    const __nv_bfloat16* __restrict__ vt,
    __nv_bfloat16* __restrict__ aob)
{
    extern __shared__ char dsm[];
    const uint32_t sb_raw = smem_u32(dsm);
    const uint32_t sb = (sb_raw + 1023u) & ~1023u;
    char* smem = dsm + (sb - sb_raw);

    const int tid = threadIdx.x;
    const int lane = tid & 31;
    const int w = tid >> 5;                    // 0..3: rows [w*32, w*32+32)
    const int i0 = blockIdx.x * 128;
    const int bh = blockIdx.y;

    const __nv_bfloat16* Qg = qt + (size_t)bh * NN * 64;
    const __nv_bfloat16* Kg = kt + (size_t)bh * NN * 64;
    const __nv_bfloat16* Vg = vt + (size_t)bh * 64 * NN;

    // ---- stage Q (128 rows x 128B = 16KB through stage-0), load A-frags ----
    #pragma unroll
    for (int i = 0; i < 8; i++) {
        int c = tid + i * 128;
        int row = c >> 3, col = c & 7;
        cp16(sb + sw128((uint32_t)(row * 128 + col * 16)),
             Qg + (size_t)(i0 + row) * 64 + col * 8);
    }
    asm volatile("cp.async.commit_group;" ::: "memory");
    asm volatile("cp.async.wait_group 0;" ::: "memory");
    __syncthreads();
    uint32_t qf[4][2][4];
    #pragma unroll
    for (int ks = 0; ks < 4; ks++)
        #pragma unroll
        for (int mf = 0; mf < 2; mf++) {
            uint32_t addr = sb + sw128((uint32_t)(
                (w * 32 + mf * 16 + (lane & 15)) * 128 + ((lane >> 4) & 1) * 16 + ks * 32));
            ldsm_x4(qf[ks][mf], addr);
        }
    __syncthreads();    // Q reads complete before stage-0 K/V overwrites

    auto issue = [&](int it, int s) {
        uint32_t kb = sb + (uint32_t)s * A_STAGE_BYTES;
        uint32_t vb = kb + 8192;
        const int j0 = it * 64;
        #pragma unroll
        for (int i = 0; i < 4; i++) {
            int c = tid + i * 128;
            int row = c >> 3, col = c & 7;
            uint32_t off = sw128((uint32_t)(row * 128 + col * 16));
            cp16(kb + off, Kg + (size_t)(j0 + row) * 64 + col * 8);
            cp16(vb + off, Vg + (size_t)row * NN + j0 + col * 8);
        }
        asm volatile("cp.async.commit_group;" ::: "memory");
    };

    issue(0, 0);
    issue(1, 1);

    float oacc[2][8][4] = {};
    float lsum[2][2] = {};

    const int NITER = NN / 64;   // 64
    int stage = 0;
    for (int it = 0; it < NITER; it++) {
        if (it < NITER - 1) asm volatile("cp.async.wait_group 1;" ::: "memory");
        else                asm volatile("cp.async.wait_group 0;" ::: "memory");
        __syncthreads();
        if (it + 2 < NITER) {
            int s2 = stage + 2; if (s2 >= A_STAGES) s2 -= A_STAGES;
            issue(it + 2, s2);
        }
        const uint32_t kb = sb + (uint32_t)stage * A_STAGE_BYTES;
        const uint32_t vb = kb + 8192;

        // ---- process 64 j in two halves of 32 to bound sacc lifetime ----
        #pragma unroll
        for (int half = 0; half < 2; half++) {
            float sacc[2][4][4] = {};          // 2 mf x 2 p x {4}
            // MMA1: S[32 rows][32 j] for p in {2*half, 2*half+1}
            #pragma unroll
            for (int ks = 0; ks < 4; ks++) {
                #pragma unroll
                for (int pp = 0; pp < 2; pp++) {
                    const int p = half * 2 + pp;
                    uint32_t r[4];
                    uint32_t addr = kb + sw128((uint32_t)(
                        (p * 16 + ((lane >> 4) << 3) + (lane & 7)) * 128 +
                        ((lane >> 3) & 1) * 16 + ks * 32));
                    ldsm_x4(r, addr);
                    #pragma unroll
                    for (int mf = 0; mf < 2; mf++) {
                        mma16816(sacc[mf][2 * pp],     qf[ks][mf], r[0], r[1]);
                        mma16816(sacc[mf][2 * pp + 1], qf[ks][mf], r[2], r[3]);
                    }
                }
            }
            // exp + pack + MMA2 for jk in {2*half, 2*half+1}
            #pragma unroll
            for (int pp = 0; pp < 2; pp++) {
                const int jk = half * 2 + pp;
                uint32_t pa[2][4];
                #pragma unroll
                for (int mf = 0; mf < 2; mf++) {
                    float e0 = ex2(sacc[mf][2 * pp][0]);
                    float e1 = ex2(sacc[mf][2 * pp][1]);
                    float e2 = ex2(sacc[mf][2 * pp][2]);
                    float e3 = ex2(sacc[mf][2 * pp][3]);
                    float e4 = ex2(sacc[mf][2 * pp + 1][0]);
                    float e5 = ex2(sacc[mf][2 * pp + 1][1]);
                    float e6 = ex2(sacc[mf][2 * pp + 1][2]);
                    float e7 = ex2(sacc[mf][2 * pp + 1][3]);
                    lsum[mf][0] += (e0 + e1) + (e4 + e5);
                    lsum[mf][1] += (e2 + e3) + (e6 + e7);
                    pa[mf][0] = pack_bf16x2(e0, e1);
                    pa[mf][1] = pack_bf16x2(e2, e3);
                    pa[mf][2] = pack_bf16x2(e4, e5);
                    pa[mf][3] = pack_bf16x2(e6, e7);
                }
                #pragma unroll
                for (int p = 0; p < 4; p++) {
                    uint32_t r[4];
                    uint32_t addr = vb + sw128((uint32_t)(
                        (p * 16 + ((lane >> 4) << 3) + (lane & 7)) * 128 +
                        ((lane >> 3) & 1) * 16 + jk * 32));
                    ldsm_x4(r, addr);
                    #pragma unroll
                    for (int mf = 0; mf < 2; mf++) {
                        mma16816(oacc[mf][2 * p],     pa[mf], r[0], r[1]);
                        mma16816(oacc[mf][2 * p + 1], pa[mf], r[2], r[3]);
                    }
                }
            }
        }
        if (++stage >= A_STAGES) stage = 0;
    }

    // ---- epilogue: quad-reduce lsum, normalize, write transposed bf16 ----
    #pragma unroll
    for (int mf = 0; mf < 2; mf++)
        #pragma unroll
        for (int h = 0; h < 2; h++) {
            lsum[mf][h] += __shfl_xor_sync(0xffffffffu, lsum[mf][h], 1);
            lsum[mf][h] += __shfl_xor_sync(0xffffffffu, lsum[mf][h], 2);
        }

    const int bq = bh >> 3, head = bh & 7;
    __nv_bfloat16* outp = aob + (size_t)bq * NN * HID + head * 64;
    #pragma unroll
    for (int mf = 0; mf < 2; mf++) {
        const float inv0 = 1.0f / lsum[mf][0];
        const float inv1 = 1.0f / lsum[mf][1];
        const int irow = i0 + w * 32 + mf * 16 + (lane >> 2);
        #pragma unroll
        for (int t = 0; t < 8; t++) {
            int d = t * 8 + (lane & 3) * 2;
            *(uint32_t*)(outp + (size_t)irow * HID + d) =
                pack_bf16x2(oacc[mf][t][0] * inv0, oacc[mf][t][1] * inv0);
            *(uint32_t*)(outp + (size_t)(irow + 8) * HID + d) =
                pack_bf16x2(oacc[mf][t][2] * inv1, oacc[mf][t][3] * inv1);
        }
    }
}

// ---------------- launch -----------------------------------------------------
extern "C" void kernel_launch(void* const* d_in, const int* in_sizes, int n_in,
                              void* d_out, int out_size)
{
    const float* x     = (const float*)d_in[0];
    const float* gamma = (const float*)d_in[1];
    const float* beta  = (const float*)d_in[2];
    const float* wq    = (const float*)d_in[3];
    const float* bq    = (const float*)d_in[4];
    const float* wk    = (const float*)d_in[5];
    const float* bk    = (const float*)d_in[6];
    const float* wv    = (const float*)d_in[7];
    const float* bv    = (const float*)d_in[8];
    const float* wo    = (const float*)d_in[9];
    const float* bo    = (const float*)d_in[10];
    float* out = (float*)d_out;

    __nv_bfloat16 *xnb, *aob, *qt, *kt, *vt, *wqb, *wkb, *wvb, *wob;
    float* gnpart;
    cudaGetSymbolAddress((void**)&xnb, g_xnb);
    cudaGetSymbolAddress((void**)&aob, g_aob);
    cudaGetSymbolAddress((void**)&qt,  g_qt);
    cudaGetSymbolAddress((void**)&kt,  g_kt);
    cudaGetSymbolAddress((void**)&vt,  g_vt);
    cudaGetSymbolAddress((void**)&wqb, g_wqb);
    cudaGetSymbolAddress((void**)&wkb, g_wkb);
    cudaGetSymbolAddress((void**)&wvb, g_wvb);
    cudaGetSymbolAddress((void**)&wob, g_wob);
    cudaGetSymbolAddress((void**)&gnpart, g_gnpart);

    cudaFuncSetAttribute(hgemm_kernel<0>,
                         cudaFuncAttributeMaxDynamicSharedMemorySize, HG_DSMEM);
    cudaFuncSetAttribute(hgemm_kernel<2>,
                         cudaFuncAttributeMaxDynamicSharedMemorySize, HG_DSMEM);
    cudaFuncSetAttribute(attn_mma_kernel,
                         cudaFuncAttributeMaxDynamicSharedMemorySize, A_SMEM);

    wconv_kernel<<<256, 256>>>(wq, wk, wv, wo, wqb, wkb, wvb, wob);
    gn_p1_kernel<<<BB * NGROUPS * 8, 256>>>(x, gnpart);
    gn_p2_kernel<<<BB * NGROUPS * 8, 256>>>(x, gamma, beta, gnpart, xnb);

    hgemm_kernel<0><<<dim3(NN / 128, 12, BB), 256, HG_DSMEM>>>(
        wqb, bq, wkb, bk, wvb, bv, xnb, qt, kt, vt, nullptr, nullptr);

    attn_mma_kernel<<<dim3(NN / 128, NBH), 128, A_SMEM>>>(qt, kt, vt, aob);

    hgemm_kernel<2><<<dim3(NN / 128, 4, BB), 256, HG_DSMEM>>>(
        wob, bo, nullptr, nullptr, nullptr, nullptr, aob, nullptr, nullptr, nullptr, x, out);
}

// round 15
// speedup vs baseline: 1.1923x; 1.1600x over previous
#include <cuda_runtime.h>
#include <cuda_bf16.h>
#include <cstdint>
#include <math.h>

#define BB 2
#define CC 512
#define NN 4096          // H*W
#define HID 512
#define NHEADS 8
#define DHEAD 64
#define NGROUPS 32
#define EPS_GN 1e-5f
#define QK_SCALE 0.35355339059327373f   // 64^(-0.25)
#define LOG2E 1.4426950408889634f
#define NBH (BB * NHEADS)               // 16

// ---------------- scratch (allocation-free rule: __device__ globals) ----------
__device__ __nv_bfloat16 g_xnb[BB * NN * CC];     // groupnormed x, transposed [b][n][c]
__device__ __nv_bfloat16 g_aob[BB * NN * HID];    // attention out, transposed [b][n][hid]
__device__ __nv_bfloat16 g_qt[NBH * NN * DHEAD];  // [bh][n][d] (scale QK*log2e)
__device__ __nv_bfloat16 g_kt[NBH * NN * DHEAD];  // [bh][n][d] (scale QK)
__device__ __nv_bfloat16 g_vt[NBH * DHEAD * NN];  // [bh][d][n]
__device__ __nv_bfloat16 g_wqb[HID * CC];
__device__ __nv_bfloat16 g_wkb[HID * CC];
__device__ __nv_bfloat16 g_wvb[HID * CC];
__device__ __nv_bfloat16 g_wob[CC * HID];
__device__ float g_gnpart[BB * NGROUPS * 8 * 2];

// ======================= helpers ==============================================
__device__ __forceinline__ uint32_t smem_u32(const void* p) {
    uint32_t a;
    asm("{ .reg .u64 t; cvta.to.shared.u64 t, %1; cvt.u32.u64 %0, t; }" : "=r"(a) : "l"(p));
    return a;
}
__device__ __forceinline__ uint32_t sw128(uint32_t off) { return off ^ ((off >> 3) & 0x70); }

__device__ __forceinline__ void ldsm_x4(uint32_t* r, uint32_t addr) {
    asm volatile("ldmatrix.sync.aligned.m8n8.x4.shared.b16 {%0,%1,%2,%3}, [%4];"
                 : "=r"(r[0]), "=r"(r[1]), "=r"(r[2]), "=r"(r[3]) : "r"(addr));
}
__device__ __forceinline__ void mma16816(float* c, const uint32_t* a, uint32_t b0, uint32_t b1) {
    asm volatile("mma.sync.aligned.m16n8k16.row.col.f32.bf16.bf16.f32 "
                 "{%0,%1,%2,%3}, {%4,%5,%6,%7}, {%8,%9}, {%0,%1,%2,%3};"
                 : "+f"(c[0]), "+f"(c[1]), "+f"(c[2]), "+f"(c[3])
                 : "r"(a[0]), "r"(a[1]), "r"(a[2]), "r"(a[3]), "r"(b0), "r"(b1));
}
__device__ __forceinline__ uint32_t pack_bf16x2(float lo, float hi) {
    uint32_t d;
    asm("cvt.rn.bf16x2.f32 %0, %1, %2;" : "=r"(d) : "f"(hi), "f"(lo));
    return d;
}
__device__ __forceinline__ unsigned short f2bf(float f) {
    unsigned short u;
    asm("cvt.rn.bf16.f32 %0, %1;" : "=h"(u) : "f"(f));
    return u;
}
__device__ __forceinline__ float ex2(float x) {
    float r;
    asm("ex2.approx.f32 %0, %1;" : "=f"(r) : "f"(x));
    return r;
}
__device__ __forceinline__ void cp16(uint32_t saddr, const void* g) {
    asm volatile("cp.async.cg.shared.global [%0], [%1], 16;" :: "r"(saddr), "l"(g));
}

// ---------------- GroupNorm phase 1 (+ fused weight conversion) ---------------
// blocks [0,512): GN partial stats. blocks [512,768): weight fp32->bf16.
__global__ void __launch_bounds__(256) gn_p1_kernel(
    const float* __restrict__ x, float* __restrict__ part,
    const float* __restrict__ wq, const float* __restrict__ wk,
    const float* __restrict__ wv, const float* __restrict__ wo,
    __nv_bfloat16* __restrict__ oq, __nv_bfloat16* __restrict__ ok,
    __nv_bfloat16* __restrict__ ov, __nv_bfloat16* __restrict__ oo)
{
    const int bid = blockIdx.x;
    if (bid >= BB * NGROUPS * 8) {
        int i = (bid - BB * NGROUPS * 8) * 256 + threadIdx.x;   // 65536 float4/matrix
        const float4* s[4] = {(const float4*)wq, (const float4*)wk,
                              (const float4*)wv, (const float4*)wo};
        __nv_bfloat16* d[4] = {oq, ok, ov, oo};
        #pragma unroll
        for (int m = 0; m < 4; m++) {
            float4 v = s[m][i];
            uint2 o;
            o.x = pack_bf16x2(v.x, v.y);
            o.y = pack_bf16x2(v.z, v.w);
            *(uint2*)(d[m] + (size_t)i * 4) = o;
        }
        return;
    }
    const int bg = bid >> 3, ch = bid & 7;
    const int b = bg / NGROUPS, g = bg % NGROUPS;
    const int c0 = g * 16;
    const int n0 = ch * 512;
    const float* xp = x + ((size_t)b * CC + c0) * NN;
    const int tid = threadIdx.x;

    float s = 0.f, s2 = 0.f;
    #pragma unroll
    for (int r = 0; r < 16; r++) {
        #pragma unroll 2
        for (int i = tid; i < 512; i += 256) {
            float v = xp[(size_t)r * NN + n0 + i];
            s += v; s2 += v * v;
        }
    }
    __shared__ float sh[512];
    sh[tid] = s; sh[tid + 256] = s2;
    __syncthreads();
    for (int st = 128; st > 0; st >>= 1) {
        if (tid < st) {
            sh[tid]       += sh[tid + st];
            sh[tid + 256] += sh[tid + 256 + st];
        }
        __syncthreads();
    }
    if (tid == 0) {
        part[bid * 2]     = sh[0];
        part[bid * 2 + 1] = sh[256];
    }
}

// ---------------- GroupNorm phase 2: normalize + transpose --------------------
__global__ void __launch_bounds__(256) gn_p2_kernel(
    const float* __restrict__ x, const float* __restrict__ gamma,
    const float* __restrict__ beta, const float* __restrict__ part,
    __nv_bfloat16* __restrict__ xnb)
{
    const int bid = blockIdx.x;
    const int bg = bid >> 3, ch = bid & 7;
    const int b = bg / NGROUPS, g = bg % NGROUPS;
    const int c0 = g * 16;
    const int n0 = ch * 512;
    const float* xp = x + ((size_t)b * CC + c0) * NN;
    const int tid = threadIdx.x;

    float sum = 0.f, ssq = 0.f;
    #pragma unroll
    for (int k = 0; k < 8; k++) {
        sum += part[(bg * 8 + k) * 2];
        ssq += part[(bg * 8 + k) * 2 + 1];
    }
    const float mean = sum * (1.0f / 65536.0f);
    const float var  = ssq * (1.0f / 65536.0f) - mean * mean;
    const float inv  = rsqrtf(var + EPS_GN);

    float ar[16], br[16];
    #pragma unroll
    for (int r = 0; r < 16; r++) {
        float gm = gamma[c0 + r];
        ar[r] = gm * inv;
        br[r] = beta[c0 + r] - mean * gm * inv;
    }

    __shared__ unsigned short T[16][264];
    __nv_bfloat16* dst0 = xnb + (size_t)b * NN * CC + c0;

    #pragma unroll
    for (int half = 0; half < 2; half++) {
        const int nb = n0 + half * 256;
        #pragma unroll
        for (int r = 0; r < 16; r++)
            T[r][tid] = f2bf(xp[(size_t)r * NN + nb + tid] * ar[r] + br[r]);
        __syncthreads();
        uint32_t u[8];
        #pragma unroll
        for (int j = 0; j < 8; j++)
            u[j] = (uint32_t)T[2 * j][tid] | ((uint32_t)T[2 * j + 1][tid] << 16);
        uint4* dp = (uint4*)(dst0 + (size_t)(nb + tid) * CC);
        dp[0] = make_uint4(u[0], u[1], u[2], u[3]);
        dp[1] = make_uint4(u[4], u[5], u[6], u[7]);
        __syncthreads();
    }
}

// ---------------- HMMA GEMM (3-stage, fully unrolled, reg-capped) --------------
// MODE 0: grid.y=12 -> q (scale QK*log2e), k (scale QK), v ([d][n])
// MODE 2: grid.y=4  -> o-proj: fp32 out + bias + residual
#define HG_DSMEM (3 * 32768 + 1024)

template<int MODE>
__global__ void __launch_bounds__(256, 2) hgemm_kernel(
    const __nv_bfloat16* __restrict__ Wq, const float* __restrict__ Bq,
    const __nv_bfloat16* __restrict__ Wk, const float* __restrict__ Bk,
    const __nv_bfloat16* __restrict__ Wv, const float* __restrict__ Bv,
    const __nv_bfloat16* __restrict__ X,
    __nv_bfloat16* __restrict__ Oq, __nv_bfloat16* __restrict__ Ok,
    __nv_bfloat16* __restrict__ Ov,
    const float* __restrict__ resid, float* __restrict__ Of)
{
    extern __shared__ char dsm[];
    const int tid = threadIdx.x, lane = tid & 31, w = tid >> 5;
    const int wm = w >> 2, wn = w & 3;
    const int n0 = blockIdx.x * 128;
    const int ty = blockIdx.y;
    const int b = blockIdx.z;

    int sel, mt;
    const __nv_bfloat16* W;
    const float* bias;
    if (MODE == 0) {
        sel = ty >> 2; mt = ty & 3;
        W = (sel == 0) ? Wq : (sel == 1) ? Wk : Wv;
        bias = (sel == 0) ? Bq : (sel == 1) ? Bk : Bv;
    } else {
        sel = 0; mt = ty; W = Wq; bias = Bq;
    }
    const int m0 = mt * 128;
    const __nv_bfloat16* Xb = X + (size_t)b * NN * CC;

    const uint32_t sb_raw = smem_u32(dsm);
    const uint32_t sb = (sb_raw + 1023u) & ~1023u;
    char* smem = dsm + (sb - sb_raw);

    auto issue = [&](int kt, int s) {
        const int k0 = kt * 64;
        uint32_t abase = sb + (uint32_t)s * 32768;
        uint32_t bbase = abase + 16384;
        #pragma unroll
        for (int i = 0; i < 4; i++) {
            int c = tid + i * 256;
            int row = c >> 3, col = c & 7;
            cp16(abase + sw128((uint32_t)(row * 128 + col * 16)),
                 W + (size_t)(m0 + row) * CC + k0 + col * 8);
            cp16(bbase + sw128((uint32_t)(row * 128 + col * 16)),
                 Xb + (size_t)(n0 + row) * CC + k0 + col * 8);
        }
        asm volatile("cp.async.commit_group;" ::: "memory");
    };

    issue(0, 0);
    issue(1, 1);

    float acc[4][4][4] = {};

    #pragma unroll
    for (int kt = 0; kt < 8; kt++) {           // fully unrolled -> static stages
        if (kt < 7) asm volatile("cp.async.wait_group 1;" ::: "memory");
        else        asm volatile("cp.async.wait_group 0;" ::: "memory");
        __syncthreads();
        if (kt + 2 < 8) issue(kt + 2, (kt + 2) % 3);
        const uint32_t abase = sb + (uint32_t)(kt % 3) * 32768;
        const uint32_t bbase = abase + 16384;
        #pragma unroll
        for (int ks = 0; ks < 4; ks++) {
            uint32_t af[4][4];
            #pragma unroll
            for (int mf = 0; mf < 4; mf++) {
                uint32_t addr = abase + sw128((uint32_t)(
                    (wm * 64 + mf * 16 + (lane & 15)) * 128 + ((lane >> 4) & 1) * 16 + ks * 32));
                ldsm_x4(af[mf], addr);
            }
            #pragma unroll
            for (int nf = 0; nf < 2; nf++) {
                uint32_t r[4];
                uint32_t addr = bbase + sw128((uint32_t)(
                    (wn * 32 + nf * 16 + ((lane >> 4) << 3) + (lane & 7)) * 128 +
                    ((lane >> 3) & 1) * 16 + ks * 32));
                ldsm_x4(r, addr);
                #pragma unroll
                for (int mf = 0; mf < 4; mf++) {
                    mma16816(acc[mf][nf * 2],     af[mf], r[0], r[1]);
                    mma16816(acc[mf][nf * 2 + 1], af[mf], r[2], r[3]);
                }
            }
        }
    }
    __syncthreads();   // all compute done before smem reuse in epilogue

    float bias_r[4][2];
    #pragma unroll
    for (int mf = 0; mf < 4; mf++) {
        int m = m0 + wm * 64 + mf * 16 + (lane >> 2);
        bias_r[mf][0] = bias[m];
        bias_r[mf][1] = bias[m + 8];
    }

    if (MODE == 2) {
        float* outp = Of + (size_t)b * CC * NN;
        const float* resb = resid + (size_t)b * CC * NN;
        #pragma unroll
        for (int mf = 0; mf < 4; mf++)
        #pragma unroll
        for (int n8 = 0; n8 < 4; n8++) {
            int rrow = m0 + wm * 64 + mf * 16 + (lane >> 2);
            int col = n0 + wn * 32 + n8 * 8 + (lane & 3) * 2;
            size_t i0x = (size_t)rrow * NN + col;
            size_t i1x = (size_t)(rrow + 8) * NN + col;
            float2 r0 = *(const float2*)(resb + i0x);
            float2 r1 = *(const float2*)(resb + i1x);
            float2 o0 = make_float2(acc[mf][n8][0] + bias_r[mf][0] + r0.x,
                                    acc[mf][n8][1] + bias_r[mf][0] + r0.y);
            float2 o1 = make_float2(acc[mf][n8][2] + bias_r[mf][1] + r1.x,
                                    acc[mf][n8][3] + bias_r[mf][1] + r1.y);
            *(float2*)(outp + i0x) = o0;
            *(float2*)(outp + i1x) = o1;
        }
    } else {
        const float scale = (sel == 0) ? QK_SCALE * LOG2E : QK_SCALE;
        unsigned short* Osm = (unsigned short*)smem;   // [128][136]
        if (sel < 2) {
            // stage transposed: Osm[n][m]
            #pragma unroll
            for (int mf = 0; mf < 4; mf++)
            #pragma unroll
            for (int n8 = 0; n8 < 4; n8++) {
                int rrow = wm * 64 + mf * 16 + (lane >> 2);
                int col = wn * 32 + n8 * 8 + (lane & 3) * 2;
                Osm[col * 136 + rrow]           = f2bf((acc[mf][n8][0] + bias_r[mf][0]) * scale);
                Osm[(col + 1) * 136 + rrow]     = f2bf((acc[mf][n8][1] + bias_r[mf][0]) * scale);
                Osm[col * 136 + rrow + 8]       = f2bf((acc[mf][n8][2] + bias_r[mf][1]) * scale);
                Osm[(col + 1) * 136 + rrow + 8] = f2bf((acc[mf][n8][3] + bias_r[mf][1]) * scale);
            }
            __syncthreads();
            int n = tid >> 1, half = tid & 1;
            int head = mt * 2 + half;
            __nv_bfloat16* outp = ((sel == 0) ? Oq : Ok) +
                ((size_t)(b * NHEADS + head) * NN + (n0 + n)) * 64;
            const uint4* src = (const uint4*)(Osm + n * 136 + half * 64);
            #pragma unroll
            for (int i = 0; i < 8; i++) ((uint4*)outp)[i] = src[i];
        } else {
            // v: stage natural: Osm[m][n]
            #pragma unroll
            for (int mf = 0; mf < 4; mf++)
            #pragma unroll
            for (int n8 = 0; n8 < 4; n8++) {
                int rrow = wm * 64 + mf * 16 + (lane >> 2);
                int col = wn * 32 + n8 * 8 + (lane & 3) * 2;
                *(uint32_t*)(Osm + rrow * 136 + col) =
                    pack_bf16x2(acc[mf][n8][0] + bias_r[mf][0], acc[mf][n8][1] + bias_r[mf][0]);
                *(uint32_t*)(Osm + (rrow + 8) * 136 + col) =
                    pack_bf16x2(acc[mf][n8][2] + bias_r[mf][1], acc[mf][n8][3] + bias_r[mf][1]);
            }
            __syncthreads();
            int m = tid >> 1, half = tid & 1;
            int mm = m0 + m;
            __nv_bfloat16* outp = Ov +
                ((size_t)(b * NHEADS + (mm >> 6)) * 64 + (mm & 63)) * NN + n0 + half * 64;
            const uint4* src = (const uint4*)(Osm + m * 136 + half * 64);
            #pragma unroll
            for (int i = 0; i < 8; i++) ((uint4*)outp)[i] = src[i];
        }
    }
}

// ---------------- HMMA flash attention (R12 config: BM=64, 4 CTAs/SM) ---------
#define A_STAGES 3
#define A_STAGE_BYTES 16384
#define A_SMEM (A_STAGES * A_STAGE_BYTES + 1024)

__global__ void __launch_bounds__(128, 4) attn_mma_kernel(
    const __nv_bfloat16* __restrict__ qt,
    const __nv_bfloat16* __restrict__ kt,
    const __nv_bfloat16* __restrict__ vt,
    __nv_bfloat16* __restrict__ aob)
{
    extern __shared__ char dsm[];
    const uint32_t sb_raw = smem_u32(dsm);
    const uint32_t sb = (sb_raw + 1023u) & ~1023u;
    char* smem = dsm + (sb - sb_raw);

    const int tid = threadIdx.x;
    const int lane = tid & 31;
    const int w = tid >> 5;                    // 0..3: rows [w*16, w*16+16)
    const int i0 = blockIdx.x * 64;
    const int bh = blockIdx.y;

    const __nv_bfloat16* Qg = qt + (size_t)bh * NN * 64;
    const __nv_bfloat16* Kg = kt + (size_t)bh * NN * 64;
    const __nv_bfloat16* Vg = vt + (size_t)bh * 64 * NN;

    // ---- stage Q (64 rows x 128B) through stage-0, load A-frags ----
    #pragma unroll
    for (int i = 0; i < 4; i++) {
        int c = tid + i * 128;
        int row = c >> 3, col = c & 7;
        cp16(sb + sw128((uint32_t)(row * 128 + col * 16)),
             Qg + (size_t)(i0 + row) * 64 + col * 8);
    }
    asm volatile("cp.async.commit_group;" ::: "memory");
    asm volatile("cp.async.wait_group 0;" ::: "memory");
    __syncthreads();
    uint32_t qf[4][4];
    #pragma unroll
    for (int ks = 0; ks < 4; ks++) {
        uint32_t addr = sb +
            sw128((uint32_t)((w * 16 + (lane & 15)) * 128 + ((lane >> 4) & 1) * 16 + ks * 32));
        ldsm_x4(qf[ks], addr);
    }
    __syncthreads();    // Q reads complete before stage-0 K/V overwrites

    auto issue = [&](int it, int s) {
        uint32_t kb = sb + (uint32_t)s * A_STAGE_BYTES;
        uint32_t vb = kb + 8192;
        const int j0 = it * 64;
        #pragma unroll
        for (int i = 0; i < 4; i++) {
            int c = tid + i * 128;
            int row = c >> 3, col = c & 7;
            uint32_t off = sw128((uint32_t)(row * 128 + col * 16));
            cp16(kb + off, Kg + (size_t)(j0 + row) * 64 + col * 8);
            cp16(vb + off, Vg + (size_t)row * NN + j0 + col * 8);
        }
        asm volatile("cp.async.commit_group;" ::: "memory");
    };

    issue(0, 0);
    issue(1, 1);

    float oacc[8][4] = {};
    float lsum0 = 0.f, lsum1 = 0.f;

    const int NITER = NN / 64;   // 64
    int stage = 0;
    for (int it = 0; it < NITER; it++) {
        if (it < NITER - 1) asm volatile("cp.async.wait_group 1;" ::: "memory");
        else                asm volatile("cp.async.wait_group 0;" ::: "memory");
        __syncthreads();
        if (it + 2 < NITER) {
            int s2 = stage + 2; if (s2 >= A_STAGES) s2 -= A_STAGES;
            issue(it + 2, s2);
        }
        const uint32_t kb = sb + (uint32_t)stage * A_STAGE_BYTES;
        const uint32_t vb = kb + 8192;

        // ---- MMA1: S[16 x 64] = Q(16x64) @ K^T ----
        float sacc[8][4] = {};
        #pragma unroll
        for (int ks = 0; ks < 4; ks++) {
            #pragma unroll
            for (int p = 0; p < 4; p++) {
                uint32_t r[4];
                uint32_t addr = kb + sw128((uint32_t)(
                    (p * 16 + ((lane >> 4) << 3) + (lane & 7)) * 128 +
                    ((lane >> 3) & 1) * 16 + ks * 32));
                ldsm_x4(r, addr);
                mma16816(sacc[2 * p],     qf[ks], r[0], r[1]);
                mma16816(sacc[2 * p + 1], qf[ks], r[2], r[3]);
            }
        }

        // ---- softmax: ex2 (log2e folded into q projection scale) ----
        #pragma unroll
        for (int t = 0; t < 8; t++) {
            float e0 = ex2(sacc[t][0]);
            float e1 = ex2(sacc[t][1]);
            float e2 = ex2(sacc[t][2]);
            float e3 = ex2(sacc[t][3]);
            sacc[t][0] = e0; sacc[t][1] = e1; sacc[t][2] = e2; sacc[t][3] = e3;
            lsum0 += e0 + e1;
            lsum1 += e2 + e3;
        }

        // ---- MMA2: O[16 x 64] += P(16x64) @ V^T(64x64) ----
        #pragma unroll
        for (int jk = 0; jk < 4; jk++) {
            uint32_t pa[4];
            pa[0] = pack_bf16x2(sacc[2 * jk][0],     sacc[2 * jk][1]);
            pa[1] = pack_bf16x2(sacc[2 * jk][2],     sacc[2 * jk][3]);
            pa[2] = pack_bf16x2(sacc[2 * jk + 1][0], sacc[2 * jk + 1][1]);
            pa[3] = pack_bf16x2(sacc[2 * jk + 1][2], sacc[2 * jk + 1][3]);
            #pragma unroll
            for (int p = 0; p < 4; p++) {
                uint32_t r[4];
                uint32_t addr = vb + sw128((uint32_t)(
                    (p * 16 + ((lane >> 4) << 3) + (lane & 7)) * 128 +
                    ((lane >> 3) & 1) * 16 + jk * 32));
                ldsm_x4(r, addr);
                mma16816(oacc[2 * p],     pa, r[0], r[1]);
                mma16816(oacc[2 * p + 1], pa, r[2], r[3]);
            }
        }
        if (++stage >= A_STAGES) stage = 0;
    }

    // ---- epilogue: normalize, write transposed bf16 directly to aob ----
    lsum0 += __shfl_xor_sync(0xffffffffu, lsum0, 1);
    lsum0 += __shfl_xor_sync(0xffffffffu, lsum0, 2);
    lsum1 += __shfl_xor_sync(0xffffffffu, lsum1, 1);
    lsum1 += __shfl_xor_sync(0xffffffffu, lsum1, 2);
    const float inv0 = 1.0f / lsum0;
    const float inv1 = 1.0f / lsum1;

    const int bq = bh >> 3, head = bh & 7;
    __nv_bfloat16* outp = aob + (size_t)bq * NN * HID + head * 64;
    const int irow = i0 + w * 16 + (lane >> 2);
    #pragma unroll
    for (int t = 0; t < 8; t++) {
        int d = t * 8 + (lane & 3) * 2;
        *(uint32_t*)(outp + (size_t)irow * HID + d) =
            pack_bf16x2(oacc[t][0] * inv0, oacc[t][1] * inv0);
        *(uint32_t*)(outp + (size_t)(irow + 8) * HID + d) =
            pack_bf16x2(oacc[t][2] * inv1, oacc[t][3] * inv1);
    }
}

// ---------------- launch -----------------------------------------------------
extern "C" void kernel_launch(void* const* d_in, const int* in_sizes, int n_in,
                              void* d_out, int out_size)
{
    const float* x     = (const float*)d_in[0];
    const float* gamma = (const float*)d_in[1];
    const float* beta  = (const float*)d_in[2];
    const float* wq    = (const float*)d_in[3];
    const float* bq    = (const float*)d_in[4];
    const float* wk    = (const float*)d_in[5];
    const float* bk    = (const float*)d_in[6];
    const float* wv    = (const float*)d_in[7];
    const float* bv    = (const float*)d_in[8];
    const float* wo    = (const float*)d_in[9];
    const float* bo    = (const float*)d_in[10];
    float* out = (float*)d_out;

    __nv_bfloat16 *xnb, *aob, *qt, *kt, *vt, *wqb, *wkb, *wvb, *wob;
    float* gnpart;
    cudaGetSymbolAddress((void**)&xnb, g_xnb);
    cudaGetSymbolAddress((void**)&aob, g_aob);
    cudaGetSymbolAddress((void**)&qt,  g_qt);
    cudaGetSymbolAddress((void**)&kt,  g_kt);
    cudaGetSymbolAddress((void**)&vt,  g_vt);
    cudaGetSymbolAddress((void**)&wqb, g_wqb);
    cudaGetSymbolAddress((void**)&wkb, g_wkb);
    cudaGetSymbolAddress((void**)&wvb, g_wvb);
    cudaGetSymbolAddress((void**)&wob, g_wob);
    cudaGetSymbolAddress((void**)&gnpart, g_gnpart);

    cudaFuncSetAttribute(hgemm_kernel<0>,
                         cudaFuncAttributeMaxDynamicSharedMemorySize, HG_DSMEM);
    cudaFuncSetAttribute(hgemm_kernel<2>,
                         cudaFuncAttributeMaxDynamicSharedMemorySize, HG_DSMEM);
    cudaFuncSetAttribute(attn_mma_kernel,
                         cudaFuncAttributeMaxDynamicSharedMemorySize, A_SMEM);

    gn_p1_kernel<<<BB * NGROUPS * 8 + 256, 256>>>(x, gnpart,
        wq, wk, wv, wo, wqb, wkb, wvb, wob);
    gn_p2_kernel<<<BB * NGROUPS * 8, 256>>>(x, gamma, beta, gnpart, xnb);

    hgemm_kernel<0><<<dim3(NN / 128, 12, BB), 256, HG_DSMEM>>>(
        wqb, bq, wkb, bk, wvb, bv, xnb, qt, kt, vt, nullptr, nullptr);

    attn_mma_kernel<<<dim3(NN / 64, NBH), 128, A_SMEM>>>(qt, kt, vt, aob);

    hgemm_kernel<2><<<dim3(NN / 128, 4, BB), 256, HG_DSMEM>>>(
        wob, bo, nullptr, nullptr, nullptr, nullptr, aob, nullptr, nullptr, nullptr, x, out);
}